// round 12
// baseline (speedup 1.0000x reference)
#include <cuda_runtime.h>
#include <cuda_bf16.h>

#define NVX 50000
#define NEX 10000
#define HD  256
#define PX  400000

// ---------------- scratch (static device globals; no runtime alloc) ----------------
__device__ float g_ve[(size_t)NVX * HD];   // relu(v @ W1^T + b1) * n_weight
__device__ float g_ev[(size_t)NEX * HD];   // relu(e_out @ W2^T + b2) * e_weight
__device__ __nv_bfloat16 g_w1h[HD * HD], g_w1l[HD * HD];
__device__ __nv_bfloat16 g_w2h[HD * HD], g_w2l[HD * HD];
__device__ int g_cnt_e[NEX];               // zero-initialized at load; re-zeroed by k_fill_all
__device__ int g_off_e[NEX + 1];
__device__ int g_cur_e[NEX];
__device__ int g_perm_e[PX];
__device__ int g_cnt_v[NVX];               // zero-initialized at load; re-zeroed by k_fill_all
__device__ int g_off_v[NVX + 1];
__device__ int g_cur_v[NVX];
__device__ int g_perm_v[PX];

__device__ __forceinline__ unsigned pack_bf16(float x0, float x1) {
    __nv_bfloat16 h0 = __float2bfloat16(x0);
    __nv_bfloat16 h1 = __float2bfloat16(x1);
    return (unsigned)__bfloat16_as_ushort(h0) | ((unsigned)__bfloat16_as_ushort(h1) << 16);
}

// ---------------- weight split pass (tiny: 2x256x256) ----------------
__global__ void k_split_w(const float* __restrict__ W1, const float* __restrict__ W2) {
    int t = blockIdx.x * blockDim.x + threadIdx.x;          // 0 .. 2*HD*HD/4-1
    const int per = HD * HD / 4;
    const float* src = (t < per) ? W1 : W2;
    __nv_bfloat16* dh = (t < per) ? g_w1h : g_w2h;
    __nv_bfloat16* dl = (t < per) ? g_w1l : g_w2l;
    size_t i = (size_t)(t < per ? t : t - per) * 4;
    float4 x = *(const float4*)&src[i];
    float h0 = __bfloat162float(__float2bfloat16(x.x));
    float h1 = __bfloat162float(__float2bfloat16(x.y));
    float h2 = __bfloat162float(__float2bfloat16(x.z));
    float h3 = __bfloat162float(__float2bfloat16(x.w));
    *(uint2*)&dh[i] = make_uint2(pack_bf16(h0, h1), pack_bf16(h2, h3));
    *(uint2*)&dl[i] = make_uint2(pack_bf16(x.x - h0, x.y - h1), pack_bf16(x.z - h2, x.w - h3));
}

// ---------------- CSR build (3 launches; counts re-zeroed by fill for next call) ----
__global__ void k_hist_all(const int* __restrict__ eidx, const int* __restrict__ vidx) {
    int i = blockIdx.x * blockDim.x + threadIdx.x;
    if (i < PX) {
        atomicAdd(&g_cnt_e[eidx[i]], 1);
        atomicAdd(&g_cnt_v[vidx[i]], 1);
    }
}

__global__ void k_scan_all() {
    const bool EDGE = (blockIdx.x == 0);
    const int n = EDGE ? NEX : NVX;
    const int items = (n + 1023) / 1024;
    const int* cnt = EDGE ? g_cnt_e : g_cnt_v;
    int* off = EDGE ? g_off_e : g_off_v;
    int* cur = EDGE ? g_cur_e : g_cur_v;

    __shared__ int wsum[32];
    int t = threadIdx.x;            // blockDim.x == 1024
    int lane = t & 31, wid = t >> 5;
    int start = t * items;
    int end = min(start + items, n);

    int sum = 0;
    for (int i = start; i < end; i++) sum += cnt[i];

    int v = sum;
#pragma unroll
    for (int s = 1; s < 32; s <<= 1) {
        int y = __shfl_up_sync(0xffffffffu, v, s);
        if (lane >= s) v += y;
    }
    if (lane == 31) wsum[wid] = v;
    __syncthreads();
    if (wid == 0) {
        int w = wsum[lane];
        int vi = w;
#pragma unroll
        for (int s = 1; s < 32; s <<= 1) {
            int y = __shfl_up_sync(0xffffffffu, vi, s);
            if (lane >= s) vi += y;
        }
        wsum[lane] = vi - w;
    }
    __syncthreads();

    int excl = wsum[wid] + (v - sum);
    int run = excl;
    for (int i = start; i < end; i++) {
        off[i] = run;
        cur[i] = run;
        run += cnt[i];
    }
    if (t == 1023) off[n] = run;
}

// fill perm, then re-zero cnt arrays (consumed by scan already) so the next
// graph replay starts from a clean histogram — replay-to-replay deterministic.
__global__ void k_fill_all(const int* __restrict__ eidx, const int* __restrict__ vidx) {
    int i = blockIdx.x * blockDim.x + threadIdx.x;
    if (i < PX) {
        int pe = atomicAdd(&g_cur_e[eidx[i]], 1);
        g_perm_e[pe] = i;
        int pv = atomicAdd(&g_cur_v[vidx[i]], 1);
        g_perm_v[pv] = i;
    }
    if (i < NEX) g_cnt_e[i] = 0;
    if (i < NVX) g_cnt_v[i] = 0;
}

// ---------------- split-bf16 tensor-core GEMM with FUSED fp32->hi/lo conversion ----
#define BM 128
#define BN 128
#define BK 32
#define SP 20            // hi/lo smem row stride in u32 (16 data + 4 pad)
#define SP32 36          // fp32 A staging row stride in u32 (32 data + 4 pad)
#define SMEM_BYTES (36864 + 2 * 10240 + 4 * 10240)   // 98304

__device__ __forceinline__ void mma_bf16(float* c, const unsigned* a, const unsigned* b) {
    asm volatile(
        "mma.sync.aligned.m16n8k16.row.col.f32.bf16.bf16.f32 "
        "{%0,%1,%2,%3}, {%4,%5,%6,%7}, {%8,%9}, {%0,%1,%2,%3};"
        : "+f"(c[0]), "+f"(c[1]), "+f"(c[2]), "+f"(c[3])
        : "r"(a[0]), "r"(a[1]), "r"(a[2]), "r"(a[3]), "r"(b[0]), "r"(b[1]));
}

__device__ __forceinline__ void cp16(unsigned* dst, const void* src) {
    unsigned s = (unsigned)__cvta_generic_to_shared(dst);
    asm volatile("cp.async.cg.shared.global [%0], [%1], 16;" :: "r"(s), "l"(src));
}

__device__ __forceinline__ void ldsm4(unsigned* r, const unsigned* p) {
    unsigned a = (unsigned)__cvta_generic_to_shared(p);
    asm volatile("ldmatrix.sync.aligned.m8n8.x4.shared.b16 {%0,%1,%2,%3}, [%4];"
        : "=r"(r[0]), "=r"(r[1]), "=r"(r[2]), "=r"(r[3]) : "r"(a));
}

__device__ __forceinline__ void ldsm2(unsigned* r, const unsigned* p) {
    unsigned a = (unsigned)__cvta_generic_to_shared(p);
    asm volatile("ldmatrix.sync.aligned.m8n8.x2.shared.b16 {%0,%1}, [%2];"
        : "=r"(r[0]), "=r"(r[1]) : "r"(a));
}

template <bool VE>
__global__ void __launch_bounds__(256, 2)
k_gemm_f32a(const float* __restrict__ A, const float* __restrict__ bias,
            const float* __restrict__ rowscale, int M) {
    const __nv_bfloat16* __restrict__ Bh = VE ? g_w1h : g_w2h;
    const __nv_bfloat16* __restrict__ Bl = VE ? g_w1l : g_w2l;
    float* C = VE ? g_ve : g_ev;

    extern __shared__ unsigned smem_u[];
    unsigned* sA32 = smem_u;                       // [2][128][36] u32 (fp32 tile)
    unsigned* sAhi = smem_u + 9216;                // [128*SP]
    unsigned* sAlo = smem_u + 9216 + 2560;         // [128*SP]
    unsigned* sBhi = smem_u + 9216 + 5120;         // [2][128*SP]
    unsigned* sBlo = smem_u + 9216 + 5120 + 5120;  // [2][128*SP]

    const int tid = threadIdx.x;
    const int bm = blockIdx.x * BM;
    const int bn = blockIdx.y * BN;
    const int wid = tid >> 5, lane = tid & 31;
    const int gid = lane >> 2, tid4 = lane & 3;
    const int wm = (wid & 1) * 64;
    const int wn = (wid >> 1) * 32;

    const int aRow = lane & 15;
    const int aCol = (lane >> 4) * 4;
    const int bRow = lane & 7;
    const int bCol = ((lane >> 3) & 1) * 4;

    const int ar0 = tid >> 2;
    const int aq0 = (tid & 3) * 2;
    const int gm0 = min(bm + ar0, M - 1);
    const int gm1 = min(bm + ar0 + 64, M - 1);
    const size_t aB0 = (size_t)gm0 * HD + aq0 * 4;
    const size_t aB1 = (size_t)gm1 * HD + aq0 * 4;

    const int crow = tid >> 1;
    const int csg = (tid & 1) * 2;
    const size_t bBase = (size_t)(bn + crow) * HD + csg * 8;
    const int dOff = crow * SP + csg * 4;

    float acc[4][4][4];
#pragma unroll
    for (int mt = 0; mt < 4; mt++)
#pragma unroll
        for (int nt = 0; nt < 4; nt++)
#pragma unroll
            for (int q = 0; q < 4; q++) acc[mt][nt][q] = 0.f;

#define CP_A(KT, BUF)                                                         \
    {                                                                         \
        unsigned* d0 = sA32 + ((BUF) * 128 + ar0) * SP32 + aq0 * 4;           \
        unsigned* d1 = sA32 + ((BUF) * 128 + ar0 + 64) * SP32 + aq0 * 4;      \
        cp16(d0,     A + aB0 + (KT) * BK);                                    \
        cp16(d0 + 4, A + aB0 + (KT) * BK + 4);                                \
        cp16(d1,     A + aB1 + (KT) * BK);                                    \
        cp16(d1 + 4, A + aB1 + (KT) * BK + 4);                                \
    }

#define CP_B(KT, BUF)                                                         \
    {                                                                         \
        int bo = (BUF) * BM * SP + dOff;                                      \
        size_t kb = bBase + (KT) * BK;                                        \
        cp16(&sBhi[bo], Bh + kb);     cp16(&sBhi[bo + 4], Bh + kb + 8);       \
        cp16(&sBlo[bo], Bl + kb);     cp16(&sBlo[bo + 4], Bl + kb + 8);       \
    }

#define CONVERT_TILE(BUF)                                                     \
    {                                                                         \
        const unsigned* s32 = sA32 + (BUF) * 128 * SP32;                      \
        int cl = tid & 31, cw = tid >> 5;                                     \
        _Pragma("unroll")                                                     \
        for (int g = 0; g < 2; g++) {                                         \
            int row = (2 * cw + g) * 8 + (cl & 7);                            \
            _Pragma("unroll")                                                 \
            for (int h2 = 0; h2 < 2; h2++) {                                  \
                int quad = (cl >> 3) + 4 * h2;                                \
                float4 f = *(const float4*)&s32[row * SP32 + quad * 4];       \
                unsigned p0 = pack_bf16(f.x, f.y);                            \
                unsigned p1 = pack_bf16(f.z, f.w);                            \
                float hx = __uint_as_float(p0 << 16);                         \
                float hy = __uint_as_float(p0 & 0xffff0000u);                 \
                float hz = __uint_as_float(p1 << 16);                         \
                float hw = __uint_as_float(p1 & 0xffff0000u);                 \
                unsigned q0 = pack_bf16(f.x - hx, f.y - hy);                  \
                unsigned q1 = pack_bf16(f.z - hz, f.w - hw);                  \
                *(uint2*)&sAhi[row * SP + quad * 2] = make_uint2(p0, p1);     \
                *(uint2*)&sAlo[row * SP + quad * 2] = make_uint2(q0, q1);     \
            }                                                                 \
        }                                                                     \
    }

#define COMPUTE_TILE(BUF)                                                     \
    {                                                                         \
        const unsigned* pBh = sBhi + (BUF) * BM * SP;                         \
        const unsigned* pBl = sBlo + (BUF) * BM * SP;                         \
        _Pragma("unroll")                                                     \
        for (int ks = 0; ks < 2; ks++) {                                      \
            unsigned ah[4][4], al[4][4];                                      \
            _Pragma("unroll")                                                 \
            for (int mt = 0; mt < 4; mt++) {                                  \
                int ao = (wm + mt * 16 + aRow) * SP + ks * 8 + aCol;          \
                ldsm4(ah[mt], sAhi + ao);                                     \
                ldsm4(al[mt], sAlo + ao);                                     \
            }                                                                 \
            _Pragma("unroll")                                                 \
            for (int nt = 0; nt < 4; nt++) {                                  \
                int bo2 = (wn + nt * 8 + bRow) * SP + ks * 8 + bCol;          \
                unsigned bh[2], bl[2];                                        \
                ldsm2(bh, pBh + bo2);                                         \
                ldsm2(bl, pBl + bo2);                                         \
                _Pragma("unroll")                                             \
                for (int mt = 0; mt < 4; mt++) {                              \
                    mma_bf16(acc[mt][nt], ah[mt], bh);                        \
                    mma_bf16(acc[mt][nt], ah[mt], bl);                        \
                    mma_bf16(acc[mt][nt], al[mt], bh);                        \
                }                                                             \
            }                                                                 \
        }                                                                     \
    }

    CP_A(0, 0); CP_B(0, 0);
    asm volatile("cp.async.commit_group;");
#pragma unroll
    for (int kt = 0; kt < HD / BK; kt++) {
        if (kt + 1 < HD / BK) { CP_A(kt + 1, (kt + 1) & 1); CP_B(kt + 1, (kt + 1) & 1); }
        asm volatile("cp.async.commit_group;");
        asm volatile("cp.async.wait_group 1;");
        __syncthreads();
        CONVERT_TILE(kt & 1);
        __syncthreads();
        COMPUTE_TILE(kt & 1);
        __syncthreads();
    }

#undef CP_A
#undef CP_B
#undef CONVERT_TILE
#undef COMPUTE_TILE

    // ---- epilogue: bias + relu + rowscale ----
#pragma unroll
    for (int mt = 0; mt < 4; mt++) {
        int rm0 = bm + wm + mt * 16 + gid;
        int rm1 = rm0 + 8;
        float sc0 = (rm0 < M) ? rowscale[rm0] : 0.f;
        float sc1 = (rm1 < M) ? rowscale[rm1] : 0.f;
#pragma unroll
        for (int nt = 0; nt < 4; nt++) {
            int cn = bn + wn + nt * 8 + tid4 * 2;
            float b0f = bias[cn], b1f = bias[cn + 1];
            if (rm0 < M) {
                float2 o;
                o.x = fmaxf(acc[mt][nt][0] + b0f, 0.f) * sc0;
                o.y = fmaxf(acc[mt][nt][1] + b1f, 0.f) * sc0;
                *(float2*)&C[(size_t)rm0 * HD + cn] = o;
            }
            if (rm1 < M) {
                float2 o;
                o.x = fmaxf(acc[mt][nt][2] + b0f, 0.f) * sc1;
                o.y = fmaxf(acc[mt][nt][3] + b1f, 0.f) * sc1;
                *(float2*)&C[(size_t)rm1 * HD + cn] = o;
            }
        }
    }
}

// ---------------- warp-per-row pull-based accumulation (dense sectors, .cg) ----
// Unroll-8 gather loop: up to 16 independent LDG.128 in flight per warp.
__global__ void k_edge_accum(const float* __restrict__ e, const int* __restrict__ pairs_v,
                             const float* __restrict__ nrw, const float* __restrict__ ers,
                             float* __restrict__ e_out) {
    int j = (blockIdx.x * blockDim.x + threadIdx.x) >> 5;
    int lane = threadIdx.x & 31;
    if (j >= NEX) return;
    int s = g_off_e[j], t = g_off_e[j + 1];

    const float4* e4 = (const float4*)&e[(size_t)j * HD];
    float4 a0 = e4[lane], a1 = e4[lane + 32];

    for (int c = s; c < t; c += 32) {
        int i = c + lane;
        int row = 0; float w = 0.f;
        if (i < t) {
            int p = g_perm_e[i];
            row = pairs_v[p];
            w = nrw[p];
        }
        int m = min(32, t - c);
#pragma unroll 8
        for (int q = 0; q < m; q++) {
            int r = __shfl_sync(0xffffffffu, row, q);
            float wq = __shfl_sync(0xffffffffu, w, q);
            const float4* src = (const float4*)&g_ve[(size_t)r * HD];
            float4 x0 = __ldcg(&src[lane]);
            float4 x1 = __ldcg(&src[lane + 32]);
            a0.x = fmaf(x0.x, wq, a0.x); a0.y = fmaf(x0.y, wq, a0.y);
            a0.z = fmaf(x0.z, wq, a0.z); a0.w = fmaf(x0.w, wq, a0.w);
            a1.x = fmaf(x1.x, wq, a1.x); a1.y = fmaf(x1.y, wq, a1.y);
            a1.z = fmaf(x1.z, wq, a1.z); a1.w = fmaf(x1.w, wq, a1.w);
        }
    }

    float inv = 1.f / ers[j];
    a0.x *= inv; a0.y *= inv; a0.z *= inv; a0.w *= inv;
    a1.x *= inv; a1.y *= inv; a1.z *= inv; a1.w *= inv;

    float4* o4 = (float4*)&e_out[(size_t)j * HD];
    o4[lane] = a0; o4[lane + 32] = a1;
}

__global__ void k_vertex_accum(const float* __restrict__ v, const int* __restrict__ pairs_e,
                               const float* __restrict__ erw, const float* __restrict__ nrs,
                               const float* __restrict__ nw, float* __restrict__ v_out) {
    int i0 = (blockIdx.x * blockDim.x + threadIdx.x) >> 5;
    int lane = threadIdx.x & 31;
    if (i0 >= NVX) return;
    int s = g_off_v[i0], t = g_off_v[i0 + 1];

    float nwi = nw[i0];
    const float4* v4 = (const float4*)&v[(size_t)i0 * HD];
    float4 a0 = v4[lane], a1 = v4[lane + 32];
    a0.x *= nwi; a0.y *= nwi; a0.z *= nwi; a0.w *= nwi;
    a1.x *= nwi; a1.y *= nwi; a1.z *= nwi; a1.w *= nwi;

    for (int c = s; c < t; c += 32) {
        int i = c + lane;
        int row = 0; float w = 0.f;
        if (i < t) {
            int p = g_perm_v[i];
            row = pairs_e[p];
            w = erw[p];
        }
        int m = min(32, t - c);
#pragma unroll 8
        for (int q = 0; q < m; q++) {
            int r = __shfl_sync(0xffffffffu, row, q);
            float wq = __shfl_sync(0xffffffffu, w, q);
            const float4* src = (const float4*)&g_ev[(size_t)r * HD];
            float4 x0 = __ldcg(&src[lane]);
            float4 x1 = __ldcg(&src[lane + 32]);
            a0.x = fmaf(x0.x, wq, a0.x); a0.y = fmaf(x0.y, wq, a0.y);
            a0.z = fmaf(x0.z, wq, a0.z); a0.w = fmaf(x0.w, wq, a0.w);
            a1.x = fmaf(x1.x, wq, a1.x); a1.y = fmaf(x1.y, wq, a1.y);
            a1.z = fmaf(x1.z, wq, a1.z); a1.w = fmaf(x1.w, wq, a1.w);
        }
    }

    float inv = 1.f / nrs[i0];
    a0.x *= inv; a0.y *= inv; a0.z *= inv; a0.w *= inv;
    a1.x *= inv; a1.y *= inv; a1.z *= inv; a1.w *= inv;

    float4* o4 = (float4*)&v_out[(size_t)i0 * HD];
    o4[lane] = a0; o4[lane + 32] = a1;
}

// ---------------- launcher: fork/join two-stream graph, launches only ----------------
static cudaStream_t g_s1 = nullptr;
static cudaEvent_t g_evFork = nullptr, g_evCsr = nullptr;

extern "C" void kernel_launch(void* const* d_in, const int* in_sizes, int n_in,
                              void* d_out, int out_size) {
    const float* v            = (const float*)d_in[0];
    const float* e            = (const float*)d_in[1];
    const float* W1           = (const float*)d_in[2];
    const float* b1           = (const float*)d_in[3];
    const float* W2           = (const float*)d_in[4];
    const float* b2           = (const float*)d_in[5];
    const float* n_weight     = (const float*)d_in[6];
    const float* e_weight     = (const float*)d_in[7];
    const float* n_reg_weight = (const float*)d_in[8];
    const float* e_reg_weight = (const float*)d_in[9];
    const float* e_reg_sum    = (const float*)d_in[10];
    const float* n_reg_sum    = (const float*)d_in[11];
    const int*   pairs_v      = (const int*)d_in[12];
    const int*   eidx         = (const int*)d_in[13];
    const int*   pairs_e      = (const int*)d_in[14];
    const int*   vidx         = (const int*)d_in[15];

    float* v_out = (float*)d_out;                              // [NVX, HD]
    float* e_out = (float*)d_out + (size_t)NVX * HD;           // [NEX, HD]

    if (!g_s1) {   // one-time setup on the uncaptured correctness call
        cudaStreamCreateWithFlags(&g_s1, cudaStreamNonBlocking);
        cudaEventCreateWithFlags(&g_evFork, cudaEventDisableTiming);
        cudaEventCreateWithFlags(&g_evCsr, cudaEventDisableTiming);
        cudaFuncSetAttribute(k_gemm_f32a<true>,
                             cudaFuncAttributeMaxDynamicSharedMemorySize, SMEM_BYTES);
        cudaFuncSetAttribute(k_gemm_f32a<false>,
                             cudaFuncAttributeMaxDynamicSharedMemorySize, SMEM_BYTES);
    }

    // main: weight split (GEMM prerequisite, ~2us)
    k_split_w<<<(2 * HD * HD / 4 + 255) / 256, 256>>>(W1, W2);               // #1 main

    // fork CSR chain onto s1 (counts already zero: static init / previous fill)
    cudaEventRecord(g_evFork, 0);
    cudaStreamWaitEvent(g_s1, g_evFork, 0);
    k_hist_all<<<(PX + 255) / 256, 256, 0, g_s1>>>(eidx, vidx);              // #2 s1
    k_scan_all<<<2, 1024, 0, g_s1>>>();                                      // #3 s1

    // GEMM1 (4th submitted launch -> ncu sample window); reads v fp32 directly
    dim3 g1((NVX + BM - 1) / BM, HD / BN);
    k_gemm_f32a<true><<<g1, 256, SMEM_BYTES>>>(v, b1, n_weight, NVX);        // #4 main

    k_fill_all<<<(PX + 255) / 256, 256, 0, g_s1>>>(eidx, vidx);              // #5 s1

    // join CSR into main before the accums
    cudaEventRecord(g_evCsr, g_s1);
    cudaStreamWaitEvent(0, g_evCsr, 0);

    k_edge_accum<<<(NEX + 7) / 8, 256>>>(e, pairs_v, n_reg_weight, e_reg_sum, e_out);   // #6

    // GEMM2 reads e_out fp32 directly
    dim3 g2((NEX + BM - 1) / BM, HD / BN);
    k_gemm_f32a<false><<<g2, 256, SMEM_BYTES>>>(e_out, b2, e_weight, NEX);   // #7

    k_vertex_accum<<<(NVX + 7) / 8, 256>>>(v, pairs_e, e_reg_weight, n_reg_sum, n_weight, v_out); // #8
}

// round 15
// speedup vs baseline: 1.0582x; 1.0582x over previous
#include <cuda_runtime.h>
#include <cuda_bf16.h>
#include <cstdint>

#define NVX 50000
#define NEX 10000
#define HD  256
#define PX  400000

// ---------------- scratch (static device globals; no runtime alloc) ----------------
__device__ float g_ve[(size_t)NVX * HD];
__device__ float g_ev[(size_t)NEX * HD];
__device__ __nv_bfloat16 g_w1h[HD * HD], g_w1l[HD * HD];
__device__ __nv_bfloat16 g_w2h[HD * HD], g_w2l[HD * HD];
__device__ int g_cnt_e[NEX];
__device__ int g_off_e[NEX + 1];
__device__ int g_cur_e[NEX];
__device__ int g_perm_e[PX];
__device__ int g_cnt_v[NVX];
__device__ int g_off_v[NVX + 1];
__device__ int g_cur_v[NVX];
__device__ int g_perm_v[PX];

__device__ __forceinline__ unsigned pack_bf16(float x0, float x1) {
    __nv_bfloat16 h0 = __float2bfloat16(x0);
    __nv_bfloat16 h1 = __float2bfloat16(x1);
    return (unsigned)__bfloat16_as_ushort(h0) | ((unsigned)__bfloat16_as_ushort(h1) << 16);
}

// ---------------- weight split pass (tiny) ----------------
__global__ void k_split_w(const float* __restrict__ W1, const float* __restrict__ W2) {
    int t = blockIdx.x * blockDim.x + threadIdx.x;
    const int per = HD * HD / 4;
    const float* src = (t < per) ? W1 : W2;
    __nv_bfloat16* dh = (t < per) ? g_w1h : g_w2h;
    __nv_bfloat16* dl = (t < per) ? g_w1l : g_w2l;
    size_t i = (size_t)(t < per ? t : t - per) * 4;
    float4 x = *(const float4*)&src[i];
    float h0 = __bfloat162float(__float2bfloat16(x.x));
    float h1 = __bfloat162float(__float2bfloat16(x.y));
    float h2 = __bfloat162float(__float2bfloat16(x.z));
    float h3 = __bfloat162float(__float2bfloat16(x.w));
    *(uint2*)&dh[i] = make_uint2(pack_bf16(h0, h1), pack_bf16(h2, h3));
    *(uint2*)&dl[i] = make_uint2(pack_bf16(x.x - h0, x.y - h1), pack_bf16(x.z - h2, x.w - h3));
}

// ---------------- CSR build ----------------
__global__ void k_zero_all() {
    int i = blockIdx.x * blockDim.x + threadIdx.x;
    if (i < NEX) g_cnt_e[i] = 0;
    if (i < NVX) g_cnt_v[i] = 0;
}

__global__ void k_hist_all(const int* __restrict__ eidx, const int* __restrict__ vidx) {
    int i = blockIdx.x * blockDim.x + threadIdx.x;
    if (i < PX) {
        atomicAdd(&g_cnt_e[eidx[i]], 1);
        atomicAdd(&g_cnt_v[vidx[i]], 1);
    }
}

__global__ void k_scan_all() {
    const bool EDGE = (blockIdx.x == 0);
    const int n = EDGE ? NEX : NVX;
    const int items = (n + 1023) / 1024;
    const int* cnt = EDGE ? g_cnt_e : g_cnt_v;
    int* off = EDGE ? g_off_e : g_off_v;
    int* cur = EDGE ? g_cur_e : g_cur_v;

    __shared__ int wsum[32];
    int t = threadIdx.x;
    int lane = t & 31, wid = t >> 5;
    int start = t * items;
    int end = min(start + items, n);

    int sum = 0;
    for (int i = start; i < end; i++) sum += cnt[i];

    int v = sum;
#pragma unroll
    for (int s = 1; s < 32; s <<= 1) {
        int y = __shfl_up_sync(0xffffffffu, v, s);
        if (lane >= s) v += y;
    }
    if (lane == 31) wsum[wid] = v;
    __syncthreads();
    if (wid == 0) {
        int w = wsum[lane];
        int vi = w;
#pragma unroll
        for (int s = 1; s < 32; s <<= 1) {
            int y = __shfl_up_sync(0xffffffffu, vi, s);
            if (lane >= s) vi += y;
        }
        wsum[lane] = vi - w;
    }
    __syncthreads();

    int excl = wsum[wid] + (v - sum);
    int run = excl;
    for (int i = start; i < end; i++) {
        off[i] = run;
        cur[i] = run;
        run += cnt[i];
    }
    if (t == 1023) off[n] = run;
}

__global__ void k_fill_all(const int* __restrict__ eidx, const int* __restrict__ vidx) {
    int i = blockIdx.x * blockDim.x + threadIdx.x;
    if (i < PX) {
        int pe = atomicAdd(&g_cur_e[eidx[i]], 1);
        g_perm_e[pe] = i;
        int pv = atomicAdd(&g_cur_v[vidx[i]], 1);
        g_perm_v[pv] = i;
    }
}

// ---------------- split-bf16 mma.sync GEMM with FUSED fp32->hi/lo conversion ----
// (R11 exact — best measured GEMM on this toolchain)
#define BM 128
#define BN 128
#define BK 32
#define SP 20
#define SP32 36
#define SMEM_BYTES (36864 + 2 * 10240 + 4 * 10240)   // 98304

__device__ __forceinline__ void mma_bf16(float* c, const unsigned* a, const unsigned* b) {
    asm volatile(
        "mma.sync.aligned.m16n8k16.row.col.f32.bf16.bf16.f32 "
        "{%0,%1,%2,%3}, {%4,%5,%6,%7}, {%8,%9}, {%0,%1,%2,%3};"
        : "+f"(c[0]), "+f"(c[1]), "+f"(c[2]), "+f"(c[3])
        : "r"(a[0]), "r"(a[1]), "r"(a[2]), "r"(a[3]), "r"(b[0]), "r"(b[1]));
}

__device__ __forceinline__ void cp16(unsigned* dst, const void* src) {
    unsigned s = (unsigned)__cvta_generic_to_shared(dst);
    asm volatile("cp.async.cg.shared.global [%0], [%1], 16;" :: "r"(s), "l"(src));
}

__device__ __forceinline__ void ldsm4(unsigned* r, const unsigned* p) {
    unsigned a = (unsigned)__cvta_generic_to_shared(p);
    asm volatile("ldmatrix.sync.aligned.m8n8.x4.shared.b16 {%0,%1,%2,%3}, [%4];"
        : "=r"(r[0]), "=r"(r[1]), "=r"(r[2]), "=r"(r[3]) : "r"(a));
}

__device__ __forceinline__ void ldsm2(unsigned* r, const unsigned* p) {
    unsigned a = (unsigned)__cvta_generic_to_shared(p);
    asm volatile("ldmatrix.sync.aligned.m8n8.x2.shared.b16 {%0,%1}, [%2];"
        : "=r"(r[0]), "=r"(r[1]) : "r"(a));
}

template <bool VE>
__global__ void __launch_bounds__(256, 2)
k_gemm_f32a(const float* __restrict__ A, const float* __restrict__ bias,
            const float* __restrict__ rowscale, int M) {
    const __nv_bfloat16* __restrict__ Bh = VE ? g_w1h : g_w2h;
    const __nv_bfloat16* __restrict__ Bl = VE ? g_w1l : g_w2l;
    float* C = VE ? g_ve : g_ev;

    extern __shared__ unsigned smem_u[];
    unsigned* sA32 = smem_u;                       // [2][128][36] u32 (fp32 tile)
    unsigned* sAhi = smem_u + 9216;                // [128*SP]
    unsigned* sAlo = smem_u + 9216 + 2560;         // [128*SP]
    unsigned* sBhi = smem_u + 9216 + 5120;         // [2][128*SP]
    unsigned* sBlo = smem_u + 9216 + 5120 + 5120;  // [2][128*SP]

    const int tid = threadIdx.x;
    const int bm = blockIdx.x * BM;
    const int bn = blockIdx.y * BN;
    const int wid = tid >> 5, lane = tid & 31;
    const int gid = lane >> 2, tid4 = lane & 3;
    const int wm = (wid & 1) * 64;
    const int wn = (wid >> 1) * 32;

    const int aRow = lane & 15;
    const int aCol = (lane >> 4) * 4;
    const int bRow = lane & 7;
    const int bCol = ((lane >> 3) & 1) * 4;

    const int ar0 = tid >> 2;
    const int aq0 = (tid & 3) * 2;
    const int gm0 = min(bm + ar0, M - 1);
    const int gm1 = min(bm + ar0 + 64, M - 1);
    const size_t aB0 = (size_t)gm0 * HD + aq0 * 4;
    const size_t aB1 = (size_t)gm1 * HD + aq0 * 4;

    const int crow = tid >> 1;
    const int csg = (tid & 1) * 2;
    const size_t bBase = (size_t)(bn + crow) * HD + csg * 8;
    const int dOff = crow * SP + csg * 4;

    float acc[4][4][4];
#pragma unroll
    for (int mt = 0; mt < 4; mt++)
#pragma unroll
        for (int nt = 0; nt < 4; nt++)
#pragma unroll
            for (int q = 0; q < 4; q++) acc[mt][nt][q] = 0.f;

#define CP_A(KT, BUF)                                                         \
    {                                                                         \
        unsigned* d0 = sA32 + ((BUF) * 128 + ar0) * SP32 + aq0 * 4;           \
        unsigned* d1 = sA32 + ((BUF) * 128 + ar0 + 64) * SP32 + aq0 * 4;      \
        cp16(d0,     A + aB0 + (KT) * BK);                                    \
        cp16(d0 + 4, A + aB0 + (KT) * BK + 4);                                \
        cp16(d1,     A + aB1 + (KT) * BK);                                    \
        cp16(d1 + 4, A + aB1 + (KT) * BK + 4);                                \
    }

#define CP_B(KT, BUF)                                                         \
    {                                                                         \
        int bo = (BUF) * BM * SP + dOff;                                      \
        size_t kb = bBase + (KT) * BK;                                        \
        cp16(&sBhi[bo], Bh + kb);     cp16(&sBhi[bo + 4], Bh + kb + 8);       \
        cp16(&sBlo[bo], Bl + kb);     cp16(&sBlo[bo + 4], Bl + kb + 8);       \
    }

#define CONVERT_TILE(BUF)                                                     \
    {                                                                         \
        const unsigned* s32 = sA32 + (BUF) * 128 * SP32;                      \
        int cl = tid & 31, cw = tid >> 5;                                     \
        _Pragma("unroll")                                                     \
        for (int g = 0; g < 2; g++) {                                         \
            int row = (2 * cw + g) * 8 + (cl & 7);                            \
            _Pragma("unroll")                                                 \
            for (int h2 = 0; h2 < 2; h2++) {                                  \
                int quad = (cl >> 3) + 4 * h2;                                \
                float4 f = *(const float4*)&s32[row * SP32 + quad * 4];       \
                unsigned p0 = pack_bf16(f.x, f.y);                            \
                unsigned p1 = pack_bf16(f.z, f.w);                            \
                float hx = __uint_as_float(p0 << 16);                         \
                float hy = __uint_as_float(p0 & 0xffff0000u);                 \
                float hz = __uint_as_float(p1 << 16);                         \
                float hw = __uint_as_float(p1 & 0xffff0000u);                 \
                unsigned q0 = pack_bf16(f.x - hx, f.y - hy);                  \
                unsigned q1 = pack_bf16(f.z - hz, f.w - hw);                  \
                *(uint2*)&sAhi[row * SP + quad * 2] = make_uint2(p0, p1);     \
                *(uint2*)&sAlo[row * SP + quad * 2] = make_uint2(q0, q1);     \
            }                                                                 \
        }                                                                     \
    }

#define COMPUTE_TILE(BUF)                                                     \
    {                                                                         \
        const unsigned* pBh = sBhi + (BUF) * BM * SP;                         \
        const unsigned* pBl = sBlo + (BUF) * BM * SP;                         \
        _Pragma("unroll")                                                     \
        for (int ks = 0; ks < 2; ks++) {                                      \
            unsigned ah[4][4], al[4][4];                                      \
            _Pragma("unroll")                                                 \
            for (int mt = 0; mt < 4; mt++) {                                  \
                int ao = (wm + mt * 16 + aRow) * SP + ks * 8 + aCol;          \
                ldsm4(ah[mt], sAhi + ao);                                     \
                ldsm4(al[mt], sAlo + ao);                                     \
            }                                                                 \
            _Pragma("unroll")                                                 \
            for (int nt = 0; nt < 4; nt++) {                                  \
                int bo2 = (wn + nt * 8 + bRow) * SP + ks * 8 + bCol;          \
                unsigned bh[2], bl[2];                                        \
                ldsm2(bh, pBh + bo2);                                         \
                ldsm2(bl, pBl + bo2);                                         \
                _Pragma("unroll")                                             \
                for (int mt = 0; mt < 4; mt++) {                              \
                    mma_bf16(acc[mt][nt], ah[mt], bh);                        \
                    mma_bf16(acc[mt][nt], ah[mt], bl);                        \
                    mma_bf16(acc[mt][nt], al[mt], bh);                        \
                }                                                             \
            }                                                                 \
        }                                                                     \
    }

    CP_A(0, 0); CP_B(0, 0);
    asm volatile("cp.async.commit_group;");
#pragma unroll
    for (int kt = 0; kt < HD / BK; kt++) {
        if (kt + 1 < HD / BK) { CP_A(kt + 1, (kt + 1) & 1); CP_B(kt + 1, (kt + 1) & 1); }
        asm volatile("cp.async.commit_group;");
        asm volatile("cp.async.wait_group 1;");
        __syncthreads();
        CONVERT_TILE(kt & 1);
        __syncthreads();
        COMPUTE_TILE(kt & 1);
        __syncthreads();
    }

#undef CP_A
#undef CP_B
#undef CONVERT_TILE
#undef COMPUTE_TILE

    // ---- epilogue: bias + relu + rowscale ----
#pragma unroll
    for (int mt = 0; mt < 4; mt++) {
        int rm0 = bm + wm + mt * 16 + gid;
        int rm1 = rm0 + 8;
        float sc0 = (rm0 < M) ? rowscale[rm0] : 0.f;
        float sc1 = (rm1 < M) ? rowscale[rm1] : 0.f;
#pragma unroll
        for (int nt = 0; nt < 4; nt++) {
            int cn = bn + wn + nt * 8 + tid4 * 2;
            float b0f = bias[cn], b1f = bias[cn + 1];
            if (rm0 < M) {
                float2 o;
                o.x = fmaxf(acc[mt][nt][0] + b0f, 0.f) * sc0;
                o.y = fmaxf(acc[mt][nt][1] + b1f, 0.f) * sc0;
                *(float2*)&C[(size_t)rm0 * HD + cn] = o;
            }
            if (rm1 < M) {
                float2 o;
                o.x = fmaxf(acc[mt][nt][2] + b0f, 0.f) * sc1;
                o.y = fmaxf(acc[mt][nt][3] + b1f, 0.f) * sc1;
                *(float2*)&C[(size_t)rm1 * HD + cn] = o;
            }
        }
    }
}

// ---------------- half-row-per-warp pull-based accumulation ----------------
// Two warps per output row: warp w -> row (w>>1), column half (w&1).
// Lane owns one dense float4 -> per incidence entry: 1 LDG.128 + 4 FMA.
// Doubles resident warps / MLP vs full-row version; traffic identical.
__global__ void k_edge_accum(const float* __restrict__ e, const int* __restrict__ pairs_v,
                             const float* __restrict__ nrw, const float* __restrict__ ers,
                             float* __restrict__ e_out) {
    int gw = (blockIdx.x * blockDim.x + threadIdx.x) >> 5;
    int j = gw >> 1;
    int half = gw & 1;
    int lane = threadIdx.x & 31;
    if (j >= NEX) return;
    int s = g_off_e[j], t = g_off_e[j + 1];

    const int f4 = half * 32 + lane;           // float4 index within row
    float4 a = ((const float4*)&e[(size_t)j * HD])[f4];

    for (int c = s; c < t; c += 32) {
        int i = c + lane;
        int row = 0; float w = 0.f;
        if (i < t) {
            int p = g_perm_e[i];
            row = pairs_v[p];
            w = nrw[p];
        }
        int m = min(32, t - c);
#pragma unroll 4
        for (int q = 0; q < m; q++) {
            int r = __shfl_sync(0xffffffffu, row, q);
            float wq = __shfl_sync(0xffffffffu, w, q);
            float4 x = __ldcg(&((const float4*)&g_ve[(size_t)r * HD])[f4]);
            a.x = fmaf(x.x, wq, a.x); a.y = fmaf(x.y, wq, a.y);
            a.z = fmaf(x.z, wq, a.z); a.w = fmaf(x.w, wq, a.w);
        }
    }

    float inv = 1.f / ers[j];
    a.x *= inv; a.y *= inv; a.z *= inv; a.w *= inv;
    ((float4*)&e_out[(size_t)j * HD])[f4] = a;
}

__global__ void k_vertex_accum(const float* __restrict__ v, const int* __restrict__ pairs_e,
                               const float* __restrict__ erw, const float* __restrict__ nrs,
                               const float* __restrict__ nw, float* __restrict__ v_out) {
    int gw = (blockIdx.x * blockDim.x + threadIdx.x) >> 5;
    int i0 = gw >> 1;
    int half = gw & 1;
    int lane = threadIdx.x & 31;
    if (i0 >= NVX) return;
    int s = g_off_v[i0], t = g_off_v[i0 + 1];

    const int f4 = half * 32 + lane;
    float nwi = nw[i0];
    float4 a = ((const float4*)&v[(size_t)i0 * HD])[f4];
    a.x *= nwi; a.y *= nwi; a.z *= nwi; a.w *= nwi;

    for (int c = s; c < t; c += 32) {
        int i = c + lane;
        int row = 0; float w = 0.f;
        if (i < t) {
            int p = g_perm_v[i];
            row = pairs_e[p];
            w = erw[p];
        }
        int m = min(32, t - c);
#pragma unroll 4
        for (int q = 0; q < m; q++) {
            int r = __shfl_sync(0xffffffffu, row, q);
            float wq = __shfl_sync(0xffffffffu, w, q);
            float4 x = __ldcg(&((const float4*)&g_ev[(size_t)r * HD])[f4]);
            a.x = fmaf(x.x, wq, a.x); a.y = fmaf(x.y, wq, a.y);
            a.z = fmaf(x.z, wq, a.z); a.w = fmaf(x.w, wq, a.w);
        }
    }

    float inv = 1.f / nrs[i0];
    a.x *= inv; a.y *= inv; a.z *= inv; a.w *= inv;
    ((float4*)&v_out[(size_t)i0 * HD])[f4] = a;
}

// ---------------- launcher: R11 fork/join topology, launches only ----------------
static cudaStream_t g_s1 = nullptr;
static cudaEvent_t g_evFork = nullptr, g_evCsr = nullptr;

extern "C" void kernel_launch(void* const* d_in, const int* in_sizes, int n_in,
                              void* d_out, int out_size) {
    const float* v            = (const float*)d_in[0];
    const float* e            = (const float*)d_in[1];
    const float* W1           = (const float*)d_in[2];
    const float* b1           = (const float*)d_in[3];
    const float* W2           = (const float*)d_in[4];
    const float* b2           = (const float*)d_in[5];
    const float* n_weight     = (const float*)d_in[6];
    const float* e_weight     = (const float*)d_in[7];
    const float* n_reg_weight = (const float*)d_in[8];
    const float* e_reg_weight = (const float*)d_in[9];
    const float* e_reg_sum    = (const float*)d_in[10];
    const float* n_reg_sum    = (const float*)d_in[11];
    const int*   pairs_v      = (const int*)d_in[12];
    const int*   eidx         = (const int*)d_in[13];
    const int*   pairs_e      = (const int*)d_in[14];
    const int*   vidx         = (const int*)d_in[15];

    float* v_out = (float*)d_out;
    float* e_out = (float*)d_out + (size_t)NVX * HD;

    if (!g_s1) {
        cudaStreamCreateWithFlags(&g_s1, cudaStreamNonBlocking);
        cudaEventCreateWithFlags(&g_evFork, cudaEventDisableTiming);
        cudaEventCreateWithFlags(&g_evCsr, cudaEventDisableTiming);
        cudaFuncSetAttribute(k_gemm_f32a<true>,
                             cudaFuncAttributeMaxDynamicSharedMemorySize, SMEM_BYTES);
        cudaFuncSetAttribute(k_gemm_f32a<false>,
                             cudaFuncAttributeMaxDynamicSharedMemorySize, SMEM_BYTES);
    }

    // main: weight split (GEMM prerequisite, ~2us)
    k_split_w<<<(2 * HD * HD / 4 + 255) / 256, 256>>>(W1, W2);               // #1 main

    // fork CSR chain onto s1
    cudaEventRecord(g_evFork, 0);
    cudaStreamWaitEvent(g_s1, g_evFork, 0);
    k_zero_all<<<(NVX + 255) / 256, 256, 0, g_s1>>>();                       // #2 s1
    k_hist_all<<<(PX + 255) / 256, 256, 0, g_s1>>>(eidx, vidx);              // #3 s1

    // GEMM1 (4th submitted launch -> ncu sample window); reads v fp32 directly
    dim3 g1((NVX + BM - 1) / BM, HD / BN);
    k_gemm_f32a<true><<<g1, 256, SMEM_BYTES>>>(v, b1, n_weight, NVX);        // #4 main

    k_scan_all<<<2, 1024, 0, g_s1>>>();                                      // #5 s1
    k_fill_all<<<(PX + 255) / 256, 256, 0, g_s1>>>(eidx, vidx);              // #6 s1

    // join CSR into main before the accums
    cudaEventRecord(g_evCsr, g_s1);
    cudaStreamWaitEvent(0, g_evCsr, 0);

    // half-row accums: 2 warps per row, 8 warps per block
    k_edge_accum<<<(2 * NEX + 7) / 8, 256>>>(e, pairs_v, n_reg_weight, e_reg_sum, e_out); // #7

    // GEMM2 reads e_out fp32 directly
    dim3 g2((NEX + BM - 1) / BM, HD / BN);
    k_gemm_f32a<false><<<g2, 256, SMEM_BYTES>>>(e_out, b2, e_weight, NEX);   // #8

    k_vertex_accum<<<(2 * NVX + 7) / 8, 256>>>(v, pairs_e, e_reg_weight, n_reg_sum, n_weight, v_out); // #9
}

// round 16
// speedup vs baseline: 1.1482x; 1.0851x over previous
#include <cuda_runtime.h>
#include <cuda_bf16.h>
#include <cstdint>

#define NVX 50000
#define NEX 10000
#define HD  256
#define PX  400000

// ---------------- scratch (static device globals; no runtime alloc) ----------------
__device__ float g_ve[(size_t)NVX * HD];
__device__ float g_ev[(size_t)NEX * HD];
__device__ __nv_bfloat16 g_w1h[HD * HD], g_w1l[HD * HD];
__device__ __nv_bfloat16 g_w2h[HD * HD], g_w2l[HD * HD];
__device__ int g_cnt_e[NEX];
__device__ int g_off_e[NEX + 1];
__device__ int g_cur_e[NEX];
__device__ int g_cnt_v[NVX];
__device__ int g_off_v[NVX + 1];
__device__ int g_cur_v[NVX];
__device__ int2 g_gat_e[PX];   // {src_vertex_row, n_reg_weight bits} per permuted slot
__device__ int2 g_gat_v[PX];   // {src_edge_row,  e_reg_weight bits} per permuted slot

__device__ __forceinline__ unsigned pack_bf16(float x0, float x1) {
    __nv_bfloat16 h0 = __float2bfloat16(x0);
    __nv_bfloat16 h1 = __float2bfloat16(x1);
    return (unsigned)__bfloat16_as_ushort(h0) | ((unsigned)__bfloat16_as_ushort(h1) << 16);
}

// ---------------- weight split pass (tiny) ----------------
__global__ void k_split_w(const float* __restrict__ W1, const float* __restrict__ W2) {
    int t = blockIdx.x * blockDim.x + threadIdx.x;
    const int per = HD * HD / 4;
    const float* src = (t < per) ? W1 : W2;
    __nv_bfloat16* dh = (t < per) ? g_w1h : g_w2h;
    __nv_bfloat16* dl = (t < per) ? g_w1l : g_w2l;
    size_t i = (size_t)(t < per ? t : t - per) * 4;
    float4 x = *(const float4*)&src[i];
    float h0 = __bfloat162float(__float2bfloat16(x.x));
    float h1 = __bfloat162float(__float2bfloat16(x.y));
    float h2 = __bfloat162float(__float2bfloat16(x.z));
    float h3 = __bfloat162float(__float2bfloat16(x.w));
    *(uint2*)&dh[i] = make_uint2(pack_bf16(h0, h1), pack_bf16(h2, h3));
    *(uint2*)&dl[i] = make_uint2(pack_bf16(x.x - h0, x.y - h1), pack_bf16(x.z - h2, x.w - h3));
}

// ---------------- CSR build ----------------
__global__ void k_zero_all() {
    int i = blockIdx.x * blockDim.x + threadIdx.x;
    if (i < NEX) g_cnt_e[i] = 0;
    if (i < NVX) g_cnt_v[i] = 0;
}

__global__ void k_hist_all(const int* __restrict__ eidx, const int* __restrict__ vidx) {
    int i = blockIdx.x * blockDim.x + threadIdx.x;
    if (i < PX) {
        atomicAdd(&g_cnt_e[eidx[i]], 1);
        atomicAdd(&g_cnt_v[vidx[i]], 1);
    }
}

__global__ void k_scan_all() {
    const bool EDGE = (blockIdx.x == 0);
    const int n = EDGE ? NEX : NVX;
    const int items = (n + 1023) / 1024;
    const int* cnt = EDGE ? g_cnt_e : g_cnt_v;
    int* off = EDGE ? g_off_e : g_off_v;
    int* cur = EDGE ? g_cur_e : g_cur_v;

    __shared__ int wsum[32];
    int t = threadIdx.x;
    int lane = t & 31, wid = t >> 5;
    int start = t * items;
    int end = min(start + items, n);

    int sum = 0;
    for (int i = start; i < end; i++) sum += cnt[i];

    int v = sum;
#pragma unroll
    for (int s = 1; s < 32; s <<= 1) {
        int y = __shfl_up_sync(0xffffffffu, v, s);
        if (lane >= s) v += y;
    }
    if (lane == 31) wsum[wid] = v;
    __syncthreads();
    if (wid == 0) {
        int w = wsum[lane];
        int vi = w;
#pragma unroll
        for (int s = 1; s < 32; s <<= 1) {
            int y = __shfl_up_sync(0xffffffffu, vi, s);
            if (lane >= s) vi += y;
        }
        wsum[lane] = vi - w;
    }
    __syncthreads();

    int excl = wsum[wid] + (v - sum);
    int run = excl;
    for (int i = start; i < end; i++) {
        off[i] = run;
        cur[i] = run;
        run += cnt[i];
    }
    if (t == 1023) off[n] = run;
}

// fill: write fused gather metadata {src_row, weight} per permuted slot.
__global__ void k_fill_all(const int* __restrict__ eidx, const int* __restrict__ vidx,
                           const int* __restrict__ pairs_v, const float* __restrict__ nrw,
                           const int* __restrict__ pairs_e, const float* __restrict__ erw) {
    int i = blockIdx.x * blockDim.x + threadIdx.x;
    if (i < PX) {
        int pe = atomicAdd(&g_cur_e[eidx[i]], 1);
        g_gat_e[pe] = make_int2(pairs_v[i], __float_as_int(nrw[i]));
        int pv = atomicAdd(&g_cur_v[vidx[i]], 1);
        g_gat_v[pv] = make_int2(pairs_e[i], __float_as_int(erw[i]));
    }
}

// ---------------- split-bf16 mma.sync GEMM with FUSED fp32->hi/lo conversion ----
// (R11 exact — best measured GEMM on this toolchain)
#define BM 128
#define BN 128
#define BK 32
#define SP 20
#define SP32 36
#define SMEM_BYTES (36864 + 2 * 10240 + 4 * 10240)   // 98304

__device__ __forceinline__ void mma_bf16(float* c, const unsigned* a, const unsigned* b) {
    asm volatile(
        "mma.sync.aligned.m16n8k16.row.col.f32.bf16.bf16.f32 "
        "{%0,%1,%2,%3}, {%4,%5,%6,%7}, {%8,%9}, {%0,%1,%2,%3};"
        : "+f"(c[0]), "+f"(c[1]), "+f"(c[2]), "+f"(c[3])
        : "r"(a[0]), "r"(a[1]), "r"(a[2]), "r"(a[3]), "r"(b[0]), "r"(b[1]));
}

__device__ __forceinline__ void cp16(unsigned* dst, const void* src) {
    unsigned s = (unsigned)__cvta_generic_to_shared(dst);
    asm volatile("cp.async.cg.shared.global [%0], [%1], 16;" :: "r"(s), "l"(src));
}

__device__ __forceinline__ void ldsm4(unsigned* r, const unsigned* p) {
    unsigned a = (unsigned)__cvta_generic_to_shared(p);
    asm volatile("ldmatrix.sync.aligned.m8n8.x4.shared.b16 {%0,%1,%2,%3}, [%4];"
        : "=r"(r[0]), "=r"(r[1]), "=r"(r[2]), "=r"(r[3]) : "r"(a));
}

__device__ __forceinline__ void ldsm2(unsigned* r, const unsigned* p) {
    unsigned a = (unsigned)__cvta_generic_to_shared(p);
    asm volatile("ldmatrix.sync.aligned.m8n8.x2.shared.b16 {%0,%1}, [%2];"
        : "=r"(r[0]), "=r"(r[1]) : "r"(a));
}

template <bool VE>
__global__ void __launch_bounds__(256, 2)
k_gemm_f32a(const float* __restrict__ A, const float* __restrict__ bias,
            const float* __restrict__ rowscale, int M) {
    const __nv_bfloat16* __restrict__ Bh = VE ? g_w1h : g_w2h;
    const __nv_bfloat16* __restrict__ Bl = VE ? g_w1l : g_w2l;
    float* C = VE ? g_ve : g_ev;

    extern __shared__ unsigned smem_u[];
    unsigned* sA32 = smem_u;                       // [2][128][36] u32 (fp32 tile)
    unsigned* sAhi = smem_u + 9216;                // [128*SP]
    unsigned* sAlo = smem_u + 9216 + 2560;         // [128*SP]
    unsigned* sBhi = smem_u + 9216 + 5120;         // [2][128*SP]
    unsigned* sBlo = smem_u + 9216 + 5120 + 5120;  // [2][128*SP]

    const int tid = threadIdx.x;
    const int bm = blockIdx.x * BM;
    const int bn = blockIdx.y * BN;
    const int wid = tid >> 5, lane = tid & 31;
    const int gid = lane >> 2, tid4 = lane & 3;
    const int wm = (wid & 1) * 64;
    const int wn = (wid >> 1) * 32;

    const int aRow = lane & 15;
    const int aCol = (lane >> 4) * 4;
    const int bRow = lane & 7;
    const int bCol = ((lane >> 3) & 1) * 4;

    const int ar0 = tid >> 2;
    const int aq0 = (tid & 3) * 2;
    const int gm0 = min(bm + ar0, M - 1);
    const int gm1 = min(bm + ar0 + 64, M - 1);
    const size_t aB0 = (size_t)gm0 * HD + aq0 * 4;
    const size_t aB1 = (size_t)gm1 * HD + aq0 * 4;

    const int crow = tid >> 1;
    const int csg = (tid & 1) * 2;
    const size_t bBase = (size_t)(bn + crow) * HD + csg * 8;
    const int dOff = crow * SP + csg * 4;

    float acc[4][4][4];
#pragma unroll
    for (int mt = 0; mt < 4; mt++)
#pragma unroll
        for (int nt = 0; nt < 4; nt++)
#pragma unroll
            for (int q = 0; q < 4; q++) acc[mt][nt][q] = 0.f;

#define CP_A(KT, BUF)                                                         \
    {                                                                         \
        unsigned* d0 = sA32 + ((BUF) * 128 + ar0) * SP32 + aq0 * 4;           \
        unsigned* d1 = sA32 + ((BUF) * 128 + ar0 + 64) * SP32 + aq0 * 4;      \
        cp16(d0,     A + aB0 + (KT) * BK);                                    \
        cp16(d0 + 4, A + aB0 + (KT) * BK + 4);                                \
        cp16(d1,     A + aB1 + (KT) * BK);                                    \
        cp16(d1 + 4, A + aB1 + (KT) * BK + 4);                                \
    }

#define CP_B(KT, BUF)                                                         \
    {                                                                         \
        int bo = (BUF) * BM * SP + dOff;                                      \
        size_t kb = bBase + (KT) * BK;                                        \
        cp16(&sBhi[bo], Bh + kb);     cp16(&sBhi[bo + 4], Bh + kb + 8);       \
        cp16(&sBlo[bo], Bl + kb);     cp16(&sBlo[bo + 4], Bl + kb + 8);       \
    }

#define CONVERT_TILE(BUF)                                                     \
    {                                                                         \
        const unsigned* s32 = sA32 + (BUF) * 128 * SP32;                      \
        int cl = tid & 31, cw = tid >> 5;                                     \
        _Pragma("unroll")                                                     \
        for (int g = 0; g < 2; g++) {                                         \
            int row = (2 * cw + g) * 8 + (cl & 7);                            \
            _Pragma("unroll")                                                 \
            for (int h2 = 0; h2 < 2; h2++) {                                  \
                int quad = (cl >> 3) + 4 * h2;                                \
                float4 f = *(const float4*)&s32[row * SP32 + quad * 4];       \
                unsigned p0 = pack_bf16(f.x, f.y);                            \
                unsigned p1 = pack_bf16(f.z, f.w);                            \
                float hx = __uint_as_float(p0 << 16);                         \
                float hy = __uint_as_float(p0 & 0xffff0000u);                 \
                float hz = __uint_as_float(p1 << 16);                         \
                float hw = __uint_as_float(p1 & 0xffff0000u);                 \
                unsigned q0 = pack_bf16(f.x - hx, f.y - hy);                  \
                unsigned q1 = pack_bf16(f.z - hz, f.w - hw);                  \
                *(uint2*)&sAhi[row * SP + quad * 2] = make_uint2(p0, p1);     \
                *(uint2*)&sAlo[row * SP + quad * 2] = make_uint2(q0, q1);     \
            }                                                                 \
        }                                                                     \
    }

#define COMPUTE_TILE(BUF)                                                     \
    {                                                                         \
        const unsigned* pBh = sBhi + (BUF) * BM * SP;                         \
        const unsigned* pBl = sBlo + (BUF) * BM * SP;                         \
        _Pragma("unroll")                                                     \
        for (int ks = 0; ks < 2; ks++) {                                      \
            unsigned ah[4][4], al[4][4];                                      \
            _Pragma("unroll")                                                 \
            for (int mt = 0; mt < 4; mt++) {                                  \
                int ao = (wm + mt * 16 + aRow) * SP + ks * 8 + aCol;          \
                ldsm4(ah[mt], sAhi + ao);                                     \
                ldsm4(al[mt], sAlo + ao);                                     \
            }                                                                 \
            _Pragma("unroll")                                                 \
            for (int nt = 0; nt < 4; nt++) {                                  \
                int bo2 = (wn + nt * 8 + bRow) * SP + ks * 8 + bCol;          \
                unsigned bh[2], bl[2];                                        \
                ldsm2(bh, pBh + bo2);                                         \
                ldsm2(bl, pBl + bo2);                                         \
                _Pragma("unroll")                                             \
                for (int mt = 0; mt < 4; mt++) {                              \
                    mma_bf16(acc[mt][nt], ah[mt], bh);                        \
                    mma_bf16(acc[mt][nt], ah[mt], bl);                        \
                    mma_bf16(acc[mt][nt], al[mt], bh);                        \
                }                                                             \
            }                                                                 \
        }                                                                     \
    }

    CP_A(0, 0); CP_B(0, 0);
    asm volatile("cp.async.commit_group;");
#pragma unroll
    for (int kt = 0; kt < HD / BK; kt++) {
        if (kt + 1 < HD / BK) { CP_A(kt + 1, (kt + 1) & 1); CP_B(kt + 1, (kt + 1) & 1); }
        asm volatile("cp.async.commit_group;");
        asm volatile("cp.async.wait_group 1;");
        __syncthreads();
        CONVERT_TILE(kt & 1);
        __syncthreads();
        COMPUTE_TILE(kt & 1);
        __syncthreads();
    }

#undef CP_A
#undef CP_B
#undef CONVERT_TILE
#undef COMPUTE_TILE

    // ---- epilogue: bias + relu + rowscale ----
#pragma unroll
    for (int mt = 0; mt < 4; mt++) {
        int rm0 = bm + wm + mt * 16 + gid;
        int rm1 = rm0 + 8;
        float sc0 = (rm0 < M) ? rowscale[rm0] : 0.f;
        float sc1 = (rm1 < M) ? rowscale[rm1] : 0.f;
#pragma unroll
        for (int nt = 0; nt < 4; nt++) {
            int cn = bn + wn + nt * 8 + tid4 * 2;
            float b0f = bias[cn], b1f = bias[cn + 1];
            if (rm0 < M) {
                float2 o;
                o.x = fmaxf(acc[mt][nt][0] + b0f, 0.f) * sc0;
                o.y = fmaxf(acc[mt][nt][1] + b1f, 0.f) * sc0;
                *(float2*)&C[(size_t)rm0 * HD + cn] = o;
            }
            if (rm1 < M) {
                float2 o;
                o.x = fmaxf(acc[mt][nt][2] + b0f, 0.f) * sc1;
                o.y = fmaxf(acc[mt][nt][3] + b1f, 0.f) * sc1;
                *(float2*)&C[(size_t)rm1 * HD + cn] = o;
            }
        }
    }
}

// ---------------- warp-per-row accumulation with fused gather metadata ----------
// Per 32-entry chunk: ONE int2 load (row+weight) -> shfl -> gathers.
// (Chain shortened from off->perm->pairs/w->gather to off->meta->gather.)
__global__ void k_edge_accum(const float* __restrict__ e, const float* __restrict__ ers,
                             float* __restrict__ e_out) {
    int j = (blockIdx.x * blockDim.x + threadIdx.x) >> 5;
    int lane = threadIdx.x & 31;
    if (j >= NEX) return;
    int s = g_off_e[j], t = g_off_e[j + 1];

    const float4* e4 = (const float4*)&e[(size_t)j * HD];
    float4 a0 = e4[lane], a1 = e4[lane + 32];

    for (int c = s; c < t; c += 32) {
        int i = c + lane;
        int row = 0; float w = 0.f;
        if (i < t) {
            int2 d = g_gat_e[i];
            row = d.x;
            w = __int_as_float(d.y);
        }
        int m = min(32, t - c);
#pragma unroll 4
        for (int q = 0; q < m; q++) {
            int r = __shfl_sync(0xffffffffu, row, q);
            float wq = __shfl_sync(0xffffffffu, w, q);
            const float4* src = (const float4*)&g_ve[(size_t)r * HD];
            float4 x0 = __ldcg(&src[lane]);
            float4 x1 = __ldcg(&src[lane + 32]);
            a0.x = fmaf(x0.x, wq, a0.x); a0.y = fmaf(x0.y, wq, a0.y);
            a0.z = fmaf(x0.z, wq, a0.z); a0.w = fmaf(x0.w, wq, a0.w);
            a1.x = fmaf(x1.x, wq, a1.x); a1.y = fmaf(x1.y, wq, a1.y);
            a1.z = fmaf(x1.z, wq, a1.z); a1.w = fmaf(x1.w, wq, a1.w);
        }
    }

    float inv = 1.f / ers[j];
    a0.x *= inv; a0.y *= inv; a0.z *= inv; a0.w *= inv;
    a1.x *= inv; a1.y *= inv; a1.z *= inv; a1.w *= inv;

    float4* o4 = (float4*)&e_out[(size_t)j * HD];
    o4[lane] = a0; o4[lane + 32] = a1;
}

__global__ void k_vertex_accum(const float* __restrict__ v, const float* __restrict__ nrs,
                               const float* __restrict__ nw, float* __restrict__ v_out) {
    int i0 = (blockIdx.x * blockDim.x + threadIdx.x) >> 5;
    int lane = threadIdx.x & 31;
    if (i0 >= NVX) return;
    int s = g_off_v[i0], t = g_off_v[i0 + 1];

    float nwi = nw[i0];
    const float4* v4 = (const float4*)&v[(size_t)i0 * HD];
    float4 a0 = v4[lane], a1 = v4[lane + 32];
    a0.x *= nwi; a0.y *= nwi; a0.z *= nwi; a0.w *= nwi;
    a1.x *= nwi; a1.y *= nwi; a1.z *= nwi; a1.w *= nwi;

    for (int c = s; c < t; c += 32) {
        int i = c + lane;
        int row = 0; float w = 0.f;
        if (i < t) {
            int2 d = g_gat_v[i];
            row = d.x;
            w = __int_as_float(d.y);
        }
        int m = min(32, t - c);
#pragma unroll 4
        for (int q = 0; q < m; q++) {
            int r = __shfl_sync(0xffffffffu, row, q);
            float wq = __shfl_sync(0xffffffffu, w, q);
            const float4* src = (const float4*)&g_ev[(size_t)r * HD];
            float4 x0 = __ldcg(&src[lane]);
            float4 x1 = __ldcg(&src[lane + 32]);
            a0.x = fmaf(x0.x, wq, a0.x); a0.y = fmaf(x0.y, wq, a0.y);
            a0.z = fmaf(x0.z, wq, a0.z); a0.w = fmaf(x0.w, wq, a0.w);
            a1.x = fmaf(x1.x, wq, a1.x); a1.y = fmaf(x1.y, wq, a1.y);
            a1.z = fmaf(x1.z, wq, a1.z); a1.w = fmaf(x1.w, wq, a1.w);
        }
    }

    float inv = 1.f / nrs[i0];
    a0.x *= inv; a0.y *= inv; a0.z *= inv; a0.w *= inv;
    a1.x *= inv; a1.y *= inv; a1.z *= inv; a1.w *= inv;

    float4* o4 = (float4*)&v_out[(size_t)i0 * HD];
    o4[lane] = a0; o4[lane + 32] = a1;
}

// ---------------- launcher: R11 fork/join topology, launches only ----------------
static cudaStream_t g_s1 = nullptr;
static cudaEvent_t g_evFork = nullptr, g_evCsr = nullptr;

extern "C" void kernel_launch(void* const* d_in, const int* in_sizes, int n_in,
                              void* d_out, int out_size) {
    const float* v            = (const float*)d_in[0];
    const float* e            = (const float*)d_in[1];
    const float* W1           = (const float*)d_in[2];
    const float* b1           = (const float*)d_in[3];
    const float* W2           = (const float*)d_in[4];
    const float* b2           = (const float*)d_in[5];
    const float* n_weight     = (const float*)d_in[6];
    const float* e_weight     = (const float*)d_in[7];
    const float* n_reg_weight = (const float*)d_in[8];
    const float* e_reg_weight = (const float*)d_in[9];
    const float* e_reg_sum    = (const float*)d_in[10];
    const float* n_reg_sum    = (const float*)d_in[11];
    const int*   pairs_v      = (const int*)d_in[12];
    const int*   eidx         = (const int*)d_in[13];
    const int*   pairs_e      = (const int*)d_in[14];
    const int*   vidx         = (const int*)d_in[15];

    float* v_out = (float*)d_out;
    float* e_out = (float*)d_out + (size_t)NVX * HD;

    if (!g_s1) {
        cudaStreamCreateWithFlags(&g_s1, cudaStreamNonBlocking);
        cudaEventCreateWithFlags(&g_evFork, cudaEventDisableTiming);
        cudaEventCreateWithFlags(&g_evCsr, cudaEventDisableTiming);
        cudaFuncSetAttribute(k_gemm_f32a<true>,
                             cudaFuncAttributeMaxDynamicSharedMemorySize, SMEM_BYTES);
        cudaFuncSetAttribute(k_gemm_f32a<false>,
                             cudaFuncAttributeMaxDynamicSharedMemorySize, SMEM_BYTES);
    }

    // main: weight split (GEMM prerequisite, ~2us)
    k_split_w<<<(2 * HD * HD / 4 + 255) / 256, 256>>>(W1, W2);               // #1 main

    // fork CSR chain onto s1
    cudaEventRecord(g_evFork, 0);
    cudaStreamWaitEvent(g_s1, g_evFork, 0);
    k_zero_all<<<(NVX + 255) / 256, 256, 0, g_s1>>>();                       // #2 s1
    k_hist_all<<<(PX + 255) / 256, 256, 0, g_s1>>>(eidx, vidx);              // #3 s1

    // GEMM1 (4th submitted launch -> ncu sample window); reads v fp32 directly
    dim3 g1((NVX + BM - 1) / BM, HD / BN);
    k_gemm_f32a<true><<<g1, 256, SMEM_BYTES>>>(v, b1, n_weight, NVX);        // #4 main

    k_scan_all<<<2, 1024, 0, g_s1>>>();                                      // #5 s1
    k_fill_all<<<(PX + 255) / 256, 256, 0, g_s1>>>(eidx, vidx,
        pairs_v, n_reg_weight, pairs_e, e_reg_weight);                       // #6 s1

    // join CSR into main before the accums
    cudaEventRecord(g_evCsr, g_s1);
    cudaStreamWaitEvent(0, g_evCsr, 0);

    k_edge_accum<<<(NEX + 7) / 8, 256>>>(e, e_reg_sum, e_out);               // #7

    // GEMM2 reads e_out fp32 directly
    dim3 g2((NEX + BM - 1) / BM, HD / BN);
    k_gemm_f32a<false><<<g2, 256, SMEM_BYTES>>>(e_out, b2, e_weight, NEX);   // #8

    k_vertex_accum<<<(NVX + 7) / 8, 256>>>(v, n_reg_sum, n_weight, v_out);   // #9
}